// round 5
// baseline (speedup 1.0000x reference)
#include <cuda_runtime.h>
#include <math_constants.h>
#include <cstdint>

#define SB   2
#define SS   2048
#define SD   512
#define SH   8
#define SHD  64
#define KTOP 307
#define RC   16
#define HWIN 16
#define MROWS (SB*SS)           // 4096
#define QT   ((KTOP + 31) / 32) // 10 query tiles per (b,h)

typedef unsigned long long ull;

// ---------------- f32x2 helpers (attention kernels) ------------------------------
__device__ __forceinline__ void fma2(ull& acc, ull a, ull b) {
    asm("fma.rn.f32x2 %0, %1, %2, %0;" : "+l"(acc) : "l"(a), "l"(b));
}
__device__ __forceinline__ ull mul2(ull a, ull b) {
    ull r; asm("mul.rn.f32x2 %0, %1, %2;" : "=l"(r) : "l"(a), "l"(b)); return r;
}
__device__ __forceinline__ ull pack2(float x, float y) {
    ull r; asm("mov.b64 %0, {%1, %2};" : "=l"(r) : "f"(x), "f"(y)); return r;
}
__device__ __forceinline__ float2 unpack2(ull v) {
    float2 r; asm("mov.b64 {%0, %1}, %2;" : "=f"(r.x), "=f"(r.y) : "l"(v)); return r;
}

__device__ __forceinline__ float tf32r(float a) {
    uint32_t r; asm("cvt.rna.tf32.f32 %0, %1;" : "=r"(r) : "f"(a));
    return __uint_as_float(r);
}

// mma.sync m16n8k8 tf32: D(16x8,f32) += A(16x8,tf32) * B(8x8,tf32)
#define MMA8(c, a, b) \
    asm volatile("mma.sync.aligned.m16n8k8.row.col.f32.tf32.tf32.f32 " \
        "{%0,%1,%2,%3},{%4,%5,%6,%7},{%8,%9},{%0,%1,%2,%3};" \
        : "+f"((c)[0]), "+f"((c)[1]), "+f"((c)[2]), "+f"((c)[3]) \
        : "r"((a)[0]), "r"((a)[1]), "r"((a)[2]), "r"((a)[3]), \
          "r"((b)[0]), "r"((b)[1]))

// ---------------- scratch --------------------------------------------------------
__device__ float g_Q  [(size_t)SB*SS*SD];
__device__ float g_K  [(size_t)SB*SS*SD];
__device__ float g_V  [(size_t)SB*SS*SD];
__device__ float g_H1 [(size_t)SB*SS*(SD/2)];
__device__ float g_IMP[SB*SS];
__device__ int   g_FLAG[SB*SS];
__device__ int   g_LIST[SB*KTOP];
__device__ float g_ATT[(size_t)SB*SS*SD];
__device__ float g_Ahi[(size_t)MROWS*SD];
__device__ float g_Alo[(size_t)MROWS*SD];
__device__ float g_Wthi[(size_t)2304*SD];   // rows: Wq 0, Wk 512, Wv 1024, Ws1 1536, Wo 1792
__device__ float g_Wtlo[(size_t)2304*SD];

// ---------------- split kernels ---------------------------------------------------
__global__ void split2(const float4* __restrict__ src, float4* __restrict__ hi,
                       float4* __restrict__ lo, int n4)
{
    int i = blockIdx.x * 256 + threadIdx.x;
    if (i >= n4) return;
    float4 a = src[i];
    float4 h, l;
    h.x = tf32r(a.x); l.x = tf32r(a.x - h.x);
    h.y = tf32r(a.y); l.y = tf32r(a.y - h.y);
    h.z = tf32r(a.z); l.z = tf32r(a.z - h.z);
    h.w = tf32r(a.w); l.w = tf32r(a.w - h.w);
    hi[i] = h; lo[i] = l;
}

// transpose W[k][n] -> WT[base+n][k] with hi/lo split
__global__ void wsplit(const float* __restrict__ W, int N, int base)
{
    __shared__ float t[32][33];
    int n0 = blockIdx.x * 32, k0 = blockIdx.y * 32;
    int tx = threadIdx.x, ty = threadIdx.y;   // 32 x 8
#pragma unroll
    for (int i = 0; i < 4; i++)
        t[ty + i * 8][tx] = W[(size_t)(k0 + ty + i * 8) * N + n0 + tx];
    __syncthreads();
#pragma unroll
    for (int i = 0; i < 4; i++) {
        float a = t[tx][ty + i * 8];
        float h = tf32r(a), l = tf32r(a - h);
        size_t o = (size_t)(base + n0 + ty + i * 8) * SD + k0 + tx;
        g_Wthi[o] = h; g_Wtlo[o] = l;
    }
}

// ================= mma.sync tf32 GEMM: 128x128 tile, BK=16, 8 warps ===============
// smem per stage: Ah/Al/Bh/Bl each [128][20] floats (pad-20 = conflict-free frags)
#define GP    20
#define GARR  (128 * GP)            // 2560 floats
#define GSTG  (4 * GARR)            // 10240 floats per stage
#define GSMEM (2 * GSTG * 4)        // 81920 bytes

__global__ void __launch_bounds__(256) gemm_mma(int mode,
    const float* __restrict__ Ahi, const float* __restrict__ Alo,
    const float* __restrict__ bq, const float* __restrict__ bk,
    const float* __restrict__ bv, const float* __restrict__ bs1,
    const float* __restrict__ bo, float* __restrict__ Oo)
{
    extern __shared__ __align__(16) float smf[];
    int nt = blockIdx.x, m0 = blockIdx.y * 128;
    int tid = threadIdx.x, wid = tid >> 5, lane = tid & 31;
    int wm = wid & 3, wn = wid >> 2;
    int g = lane >> 2, t4 = lane & 3;

    float* C; const float* bias; int Nc, cbase, wtrow, relu = 0, fourth = 0;
    if (mode == 0) {
        if (nt < 4)       { C = g_Q;  bias = bq;  Nc = 512; cbase = nt * 128; }
        else if (nt < 8)  { C = g_K;  bias = bk;  Nc = 512; cbase = (nt - 4) * 128; }
        else if (nt < 12) { C = g_V;  bias = bv;  Nc = 512; cbase = (nt - 8) * 128; }
        else              { C = g_H1; bias = bs1; Nc = 256; cbase = (nt - 12) * 128; relu = 1; fourth = 1; }
        wtrow = nt * 128;
    } else {
        C = Oo; bias = bo; Nc = 512; cbase = nt * 128; wtrow = 1792 + nt * 128;
    }

    float c[2][8][4];
#pragma unroll
    for (int mt = 0; mt < 2; mt++)
#pragma unroll
        for (int j = 0; j < 8; j++)
#pragma unroll
            for (int q = 0; q < 4; q++) c[mt][j][q] = 0.f;

    // loader coords: 512 float4 per array, 2 per thread
    int u0 = tid, u1 = tid + 256;
    int r0 = u0 >> 2, c0_ = (u0 & 3) * 4;
    int r1 = u1 >> 2, c1_ = (u1 & 3) * 4;

    const float* pAh = Ahi     + (size_t)m0 * SD;
    const float* pAl = Alo     + (size_t)m0 * SD;
    const float* pBh = g_Wthi + (size_t)wtrow * SD;
    const float* pBl = g_Wtlo + (size_t)wtrow * SD;

    float4 fa0h, fa1h, fa0l, fa1l, fb0h, fb1h, fb0l, fb1l;
    {
        int k0 = 0;
        fa0h = *(const float4*)(pAh + (size_t)r0 * SD + k0 + c0_);
        fa1h = *(const float4*)(pAh + (size_t)r1 * SD + k0 + c1_);
        fa0l = *(const float4*)(pAl + (size_t)r0 * SD + k0 + c0_);
        fa1l = *(const float4*)(pAl + (size_t)r1 * SD + k0 + c1_);
        fb0h = *(const float4*)(pBh + (size_t)r0 * SD + k0 + c0_);
        fb1h = *(const float4*)(pBh + (size_t)r1 * SD + k0 + c1_);
        fb0l = *(const float4*)(pBl + (size_t)r0 * SD + k0 + c0_);
        fb1l = *(const float4*)(pBl + (size_t)r1 * SD + k0 + c1_);
    }

#pragma unroll 1
    for (int it = 0; it < 32; it++) {
        float* st = smf + (it & 1) * GSTG;
        // store current tile
        *(float4*)(st + 0 * GARR + r0 * GP + c0_) = fa0h;
        *(float4*)(st + 0 * GARR + r1 * GP + c1_) = fa1h;
        *(float4*)(st + 1 * GARR + r0 * GP + c0_) = fa0l;
        *(float4*)(st + 1 * GARR + r1 * GP + c1_) = fa1l;
        *(float4*)(st + 2 * GARR + r0 * GP + c0_) = fb0h;
        *(float4*)(st + 2 * GARR + r1 * GP + c1_) = fb1h;
        *(float4*)(st + 3 * GARR + r0 * GP + c0_) = fb0l;
        *(float4*)(st + 3 * GARR + r1 * GP + c1_) = fb1l;
        __syncthreads();

        if (it + 1 < 32) {   // prefetch next
            int k0 = (it + 1) * 16;
            fa0h = *(const float4*)(pAh + (size_t)r0 * SD + k0 + c0_);
            fa1h = *(const float4*)(pAh + (size_t)r1 * SD + k0 + c1_);
            fa0l = *(const float4*)(pAl + (size_t)r0 * SD + k0 + c0_);
            fa1l = *(const float4*)(pAl + (size_t)r1 * SD + k0 + c1_);
            fb0h = *(const float4*)(pBh + (size_t)r0 * SD + k0 + c0_);
            fb1h = *(const float4*)(pBh + (size_t)r1 * SD + k0 + c1_);
            fb0l = *(const float4*)(pBl + (size_t)r0 * SD + k0 + c0_);
            fb1l = *(const float4*)(pBl + (size_t)r1 * SD + k0 + c1_);
        }

        const uint32_t* uAh = (const uint32_t*)(st + 0 * GARR);
        const uint32_t* uAl = (const uint32_t*)(st + 1 * GARR);
        const uint32_t* uBh = (const uint32_t*)(st + 2 * GARR);
        const uint32_t* uBl = (const uint32_t*)(st + 3 * GARR);

#pragma unroll
        for (int ks = 0; ks < 2; ks++) {
            int kc = ks * 8 + t4;
            uint32_t ah[2][4], al[2][4];
#pragma unroll
            for (int mt = 0; mt < 2; mt++) {
                int rr = (wm * 32 + mt * 16 + g) * GP;
                ah[mt][0] = uAh[rr + kc];            ah[mt][1] = uAh[rr + 8 * GP + kc];
                ah[mt][2] = uAh[rr + kc + 4];        ah[mt][3] = uAh[rr + 8 * GP + kc + 4];
                al[mt][0] = uAl[rr + kc];            al[mt][1] = uAl[rr + 8 * GP + kc];
                al[mt][2] = uAl[rr + kc + 4];        al[mt][3] = uAl[rr + 8 * GP + kc + 4];
            }
#pragma unroll
            for (int grp = 0; grp < 2; grp++) {
                uint32_t bh[4][2], bl[4][2];
#pragma unroll
                for (int jj = 0; jj < 4; jj++) {
                    int nr = (wn * 64 + (grp * 4 + jj) * 8 + g) * GP;
                    bh[jj][0] = uBh[nr + kc]; bh[jj][1] = uBh[nr + kc + 4];
                    bl[jj][0] = uBl[nr + kc]; bl[jj][1] = uBl[nr + kc + 4];
                }
#pragma unroll
                for (int jj = 0; jj < 4; jj++)
#pragma unroll
                    for (int mt = 0; mt < 2; mt++) {
                        float* cc = c[mt][grp * 4 + jj];
                        MMA8(cc, ah[mt], bh[jj]);
                        MMA8(cc, ah[mt], bl[jj]);
                        MMA8(cc, al[mt], bh[jj]);
                        if (fourth) MMA8(cc, al[mt], bl[jj]);
                    }
            }
        }
        __syncthreads();
    }

    // epilogue: bias (+relu), float2 stores
#pragma unroll
    for (int mt = 0; mt < 2; mt++) {
        int rowa = m0 + wm * 32 + mt * 16 + g;
#pragma unroll
        for (int j = 0; j < 8; j++) {
            int colg = cbase + wn * 64 + j * 8 + t4 * 2;
            float2 bb = *(const float2*)&bias[colg];
            float2 o0 = make_float2(c[mt][j][0] + bb.x, c[mt][j][1] + bb.y);
            float2 o1 = make_float2(c[mt][j][2] + bb.x, c[mt][j][3] + bb.y);
            if (relu) {
                o0.x = fmaxf(o0.x, 0.f); o0.y = fmaxf(o0.y, 0.f);
                o1.x = fmaxf(o1.x, 0.f); o1.y = fmaxf(o1.y, 0.f);
            }
            *(float2*)&C[(size_t)rowa * Nc + colg]       = o0;
            *(float2*)&C[(size_t)(rowa + 8) * Nc + colg] = o1;
        }
    }
}

// ---------------- importance -----------------------------------------------------
__global__ void imp_kernel(const float* __restrict__ H1, const float* __restrict__ Ws2,
                           const float* __restrict__ bs2, float* __restrict__ IMP)
{
    int row = blockIdx.x * 8 + (threadIdx.x >> 5);
    int l   = threadIdx.x & 31;
    const float* h = H1 + (size_t)row * 256;
    float acc = 0.f;
#pragma unroll
    for (int c = l; c < 256; c += 32) acc += h[c] * Ws2[c];
#pragma unroll
    for (int o = 16; o; o >>= 1) acc += __shfl_xor_sync(0xffffffffu, acc, o);
    if (l == 0) {
        float z = acc + bs2[0];
        IMP[row] = 1.f / (1.f + __expf(-z));
    }
}

// ---------------- top-k ------------------------------------------------------------
__global__ void topk_flag(const float* __restrict__ IMP, int* __restrict__ FLAG)
{
    int b = blockIdx.x, chunk = blockIdx.y;
    __shared__ float s[SS];
    for (int i = threadIdx.x; i < SS; i += 256) s[i] = IMP[b * SS + i];
    __syncthreads();
    int i = chunk * 256 + threadIdx.x;
    float vi = s[i];
    int cnt = 0;
#pragma unroll 8
    for (int j = 0; j < SS; j++) {
        float vj = s[j];
        cnt += (vj > vi) || (vj == vi && j < i);
    }
    FLAG[b * SS + i] = (cnt < KTOP) ? 1 : 0;
}

__global__ void topk_compact(const int* __restrict__ FLAG, int* __restrict__ LIST)
{
    int b = blockIdx.x;
    __shared__ int f[SS];
    __shared__ int cs[256];
    for (int i = threadIdx.x; i < SS; i += 256) f[i] = FLAG[b * SS + i];
    __syncthreads();
    int t = threadIdx.x;
    int sum = 0;
#pragma unroll
    for (int j = 0; j < 8; j++) sum += f[t * 8 + j];
    cs[t] = sum;
    __syncthreads();
#pragma unroll
    for (int off = 1; off < 256; off <<= 1) {
        int v = (t >= off) ? cs[t - off] : 0;
        __syncthreads();
        cs[t] += v;
        __syncthreads();
    }
    int pos = cs[t] - sum;
#pragma unroll
    for (int j = 0; j < 8; j++) {
        int i = t * 8 + j;
        if (f[i]) LIST[b * KTOP + pos++] = i;
    }
}

// ---------------- kernel A: non-important rows (<=33 keys) -----------------------
__global__ void attn_sparse(const float* __restrict__ Q, const float* __restrict__ K,
                            const float* __restrict__ V, const int* __restrict__ rand_idx,
                            const int* __restrict__ FLAG, float* __restrict__ ATT)
{
    int bi = blockIdx.x;
    if (FLAG[bi]) return;
    int b = bi >> 11, i = bi & (SS - 1);

    __shared__ float qsh[SD];
    __shared__ int   list[40];
    __shared__ int   nk_sh;
    __shared__ float p[SH][64];

    const float* qrow = Q + (size_t)bi * SD;
    for (int t = threadIdx.x; t < SD; t += 256) qsh[t] = qrow[t];

    if (threadIdx.x == 0) {
        int lo = i - HWIN; if (lo < 0) lo = 0;
        int n = 0;
        for (int j = lo; j <= i; j++) list[n++] = j;
        int nw = n;
        for (int r = 0; r < RC; r++) {
            int j = rand_idx[(size_t)bi * RC + r];
            if (j <= i && j < lo) {
                bool dup = false;
                for (int t = nw; t < n; t++) if (list[t] == j) { dup = true; break; }
                if (!dup) list[n++] = j;
            }
        }
        nk_sh = n;
    }
    __syncthreads();

    int h = threadIdx.x >> 5, l = threadIdx.x & 31;
    int n = nk_sh;
    const ull* qp = (const ull*)(qsh + h * SHD);

    float s0 = -CUDART_INF_F, s1 = -CUDART_INF_F;
    if (l < n) {
        const float4* kr = (const float4*)(K + ((size_t)b * SS + list[l]) * SD + h * SHD);
        ull acc = 0ull;
#pragma unroll
        for (int d4 = 0; d4 < 16; d4++) {
            float4 kv = kr[d4];
            fma2(acc, pack2(kv.x, kv.y), qp[2 * d4]);
            fma2(acc, pack2(kv.z, kv.w), qp[2 * d4 + 1]);
        }
        float2 f = unpack2(acc);
        s0 = (f.x + f.y) * 0.125f;
    }
    if (l + 32 < n) {
        const float4* kr = (const float4*)(K + ((size_t)b * SS + list[l + 32]) * SD + h * SHD);
        ull acc = 0ull;
#pragma unroll
        for (int d4 = 0; d4 < 16; d4++) {
            float4 kv = kr[d4];
            fma2(acc, pack2(kv.x, kv.y), qp[2 * d4]);
            fma2(acc, pack2(kv.z, kv.w), qp[2 * d4 + 1]);
        }
        float2 f = unpack2(acc);
        s1 = (f.x + f.y) * 0.125f;
    }
    float mx = fmaxf(s0, s1);
#pragma unroll
    for (int o = 16; o; o >>= 1) mx = fmaxf(mx, __shfl_xor_sync(0xffffffffu, mx, o));
    float e0 = (l < n)      ? __expf(s0 - mx) : 0.f;
    float e1 = (l + 32 < n) ? __expf(s1 - mx) : 0.f;
    float sum = e0 + e1;
#pragma unroll
    for (int o = 16; o; o >>= 1) sum += __shfl_xor_sync(0xffffffffu, sum, o);
    float inv = 1.f / sum;
    p[h][l] = e0;
    p[h][l + 32] = e1;
    __syncwarp();

    ull a0p = 0ull, a1p = 0ull;
    float a0t = 0.f, a1t = 0.f;
    int t = 0;
    for (; t + 1 < n; t += 2) {
        const float* v0 = V + ((size_t)b * SS + list[t])     * SD + h * SHD;
        const float* v1 = V + ((size_t)b * SS + list[t + 1]) * SD + h * SHD;
        ull pp = pack2(p[h][t], p[h][t + 1]);
        fma2(a0p, pp, pack2(v0[l],      v1[l]));
        fma2(a1p, pp, pack2(v0[l + 32], v1[l + 32]));
    }
    if (t < n) {
        const float* v0 = V + ((size_t)b * SS + list[t]) * SD + h * SHD;
        float pj = p[h][t];
        a0t = pj * v0[l];
        a1t = pj * v0[l + 32];
    }
    float2 fa0 = unpack2(a0p), fa1 = unpack2(a1p);
    float* orow = ATT + (size_t)bi * SD + h * SHD;
    orow[l]      = (fa0.x + fa0.y + a0t) * inv;
    orow[l + 32] = (fa1.x + fa1.y + a1t) * inv;
}

// ---------------- kernel B: flash-style q-tiled dense rows -----------------------
__global__ void attn_dense(const float* __restrict__ Q, const float* __restrict__ K,
                           const float* __restrict__ V, const int* __restrict__ LIST,
                           float* __restrict__ ATT)
{
    int qt = blockIdx.x, b = blockIdx.y, h = blockIdx.z;
    __shared__ float2 Qs2[32][32];
    __shared__ float2 Ks2[32][33];
    __shared__ float  Vs[32][64];
    __shared__ float  Ps[32][34];
    __shared__ int    qi[32];

    int tid = threadIdx.x, w = tid >> 5, l = tid & 31;
    int base = qt * 32;
    int nq = KTOP - base; if (nq > 32) nq = 32;
    if (tid < 32)
        qi[tid] = (tid < nq) ? LIST[b * KTOP + base + tid] : -1;
    __syncthreads();
    int imax = qi[nq - 1];

    int row = tid >> 3, d0 = (tid & 7) * 8;
    {
        int q = qi[row]; int qs = q < 0 ? 0 : q;
        const float* src = Q + ((size_t)b * SS + qs) * SD + h * SHD + d0;
        float4 a = *(const float4*)src;
        float4 c = *(const float4*)(src + 4);
        int dp = d0 >> 1;
        Qs2[row][dp + 0] = make_float2(a.x, a.y);
        Qs2[row][dp + 1] = make_float2(a.z, a.w);
        Qs2[row][dp + 2] = make_float2(c.x, c.y);
        Qs2[row][dp + 3] = make_float2(c.z, c.w);
    }

    int qg[4];
    float m[4], lsum[4];
    ull a0p[4], a1p[4];
#pragma unroll
    for (int c = 0; c < 4; c++) {
        qg[c] = qi[w * 4 + c];
        m[c] = -CUDART_INF_F; lsum[c] = 0.f; a0p[c] = 0ull; a1p[c] = 0ull;
    }

    for (int j0 = 0; j0 <= imax; j0 += 32) {
        __syncthreads();
        {
            int j = j0 + row;
            const float* kp = K + ((size_t)b * SS + j) * SD + h * SHD + d0;
            float4 ka = *(const float4*)kp;
            float4 kb = *(const float4*)(kp + 4);
            int dp = d0 >> 1;
            Ks2[dp + 0][row] = make_float2(ka.x, ka.y);
            Ks2[dp + 1][row] = make_float2(ka.z, ka.w);
            Ks2[dp + 2][row] = make_float2(kb.x, kb.y);
            Ks2[dp + 3][row] = make_float2(kb.z, kb.w);
            const float* vp = V + ((size_t)b * SS + j) * SD + h * SHD + d0;
            *(float4*)&Vs[row][d0]     = *(const float4*)vp;
            *(float4*)&Vs[row][d0 + 4] = *(const float4*)(vp + 4);
        }
        __syncthreads();

        int jg = j0 + l;
        ull acc2[4] = {0ull, 0ull, 0ull, 0ull};
        const ull* Qu = (const ull*)Qs2;
        const ull* Ku = (const ull*)Ks2;
#pragma unroll
        for (int dp = 0; dp < 32; dp++) {
            ull kp = Ku[dp * 33 + l];
#pragma unroll
            for (int c = 0; c < 4; c++)
                fma2(acc2[c], Qu[(w * 4 + c) * 32 + dp], kp);
        }
#pragma unroll
        for (int c = 0; c < 4; c++) {
            float2 sf = unpack2(acc2[c]);
            bool ok = (jg <= qg[c]);
            float sc = ok ? (sf.x + sf.y) * 0.125f : -CUDART_INF_F;
            float tm = sc;
#pragma unroll
            for (int o = 16; o; o >>= 1) tm = fmaxf(tm, __shfl_xor_sync(0xffffffffu, tm, o));
            float newm = fmaxf(m[c], tm);
            float pv = 0.f;
            if (newm != -CUDART_INF_F) {
                pv = ok ? __expf(sc - newm) : 0.f;
                float ps = pv;
#pragma unroll
                for (int o = 16; o; o >>= 1) ps += __shfl_xor_sync(0xffffffffu, ps, o);
                float scale = (m[c] == -CUDART_INF_F) ? 0.f : __expf(m[c] - newm);
                lsum[c] = lsum[c] * scale + ps;
                ull ss = pack2(scale, scale);
                a0p[c] = mul2(a0p[c], ss);
                a1p[c] = mul2(a1p[c], ss);
                m[c] = newm;
            }
            Ps[w * 4 + c][l] = pv;
        }
        __syncwarp();
#pragma unroll
        for (int jp = 0; jp < 16; jp++) {
            int j = jp * 2;
            ull vpa = pack2(Vs[j][l],      Vs[j + 1][l]);
            ull vpb = pack2(Vs[j][l + 32], Vs[j + 1][l + 32]);
#pragma unroll
            for (int c = 0; c < 4; c++) {
                ull pp = *(const ull*)&Ps[w * 4 + c][j];
                fma2(a0p[c], pp, vpa);
                fma2(a1p[c], pp, vpb);
            }
        }
    }

#pragma unroll
    for (int c = 0; c < 4; c++) {
        if (qg[c] >= 0) {
            float inv = 1.f / lsum[c];
            float2 fa = unpack2(a0p[c]);
            float2 fb = unpack2(a1p[c]);
            float* orow = ATT + ((size_t)b * SS + qg[c]) * SD + h * SHD;
            orow[l]      = (fa.x + fa.y) * inv;
            orow[l + 32] = (fb.x + fb.y) * inv;
        }
    }
}

// ---------------- launch ---------------------------------------------------------
extern "C" void kernel_launch(void* const* d_in, const int* in_sizes, int n_in,
                              void* d_out, int out_size)
{
    const float* x    = (const float*)d_in[0];
    const float* Wq   = (const float*)d_in[1];
    const float* bq   = (const float*)d_in[2];
    const float* Wk   = (const float*)d_in[3];
    const float* bk   = (const float*)d_in[4];
    const float* Wv   = (const float*)d_in[5];
    const float* bv   = (const float*)d_in[6];
    const float* Wo   = (const float*)d_in[7];
    const float* bo   = (const float*)d_in[8];
    const float* Ws1  = (const float*)d_in[9];
    const float* bs1  = (const float*)d_in[10];
    const float* Ws2  = (const float*)d_in[11];
    const float* bs2  = (const float*)d_in[12];
    const int*   ridx = (const int*)  d_in[13];
    float* out = (float*)d_out;

    float *Q, *K, *V, *H1, *IMP, *ATT, *Ahi, *Alo;
    int *FLAG, *LIST;
    cudaGetSymbolAddress((void**)&Q,   g_Q);
    cudaGetSymbolAddress((void**)&K,   g_K);
    cudaGetSymbolAddress((void**)&V,   g_V);
    cudaGetSymbolAddress((void**)&H1,  g_H1);
    cudaGetSymbolAddress((void**)&IMP, g_IMP);
    cudaGetSymbolAddress((void**)&ATT, g_ATT);
    cudaGetSymbolAddress((void**)&FLAG, g_FLAG);
    cudaGetSymbolAddress((void**)&LIST, g_LIST);
    cudaGetSymbolAddress((void**)&Ahi, g_Ahi);
    cudaGetSymbolAddress((void**)&Alo, g_Alo);

    cudaFuncSetAttribute(gemm_mma, cudaFuncAttributeMaxDynamicSharedMemorySize, GSMEM);

    const int N4 = MROWS * SD / 4;   // 524288 float4s
    split2<<<(N4 + 255) / 256, 256>>>((const float4*)x, (float4*)Ahi, (float4*)Alo, N4);
    wsplit<<<dim3(16, 16), dim3(32, 8)>>>(Wq,  512, 0);
    wsplit<<<dim3(16, 16), dim3(32, 8)>>>(Wk,  512, 512);
    wsplit<<<dim3(16, 16), dim3(32, 8)>>>(Wv,  512, 1024);
    wsplit<<<dim3(8,  16), dim3(32, 8)>>>(Ws1, 256, 1536);
    wsplit<<<dim3(16, 16), dim3(32, 8)>>>(Wo,  512, 1792);

    gemm_mma<<<dim3(14, 32), 256, GSMEM>>>(0, Ahi, Alo, bq, bk, bv, bs1, bo, out);

    imp_kernel<<<MROWS / 8, 256>>>(H1, Ws2, bs2, IMP);
    topk_flag<<<dim3(SB, 8), 256>>>(IMP, FLAG);
    topk_compact<<<SB, 256>>>(FLAG, LIST);

    attn_sparse<<<MROWS, 256>>>(Q, K, V, ridx, FLAG, ATT);
    attn_dense<<<dim3(QT, SB, SH), 256>>>(Q, K, V, LIST, ATT);

    split2<<<(N4 + 255) / 256, 256>>>((const float4*)ATT, (float4*)Ahi, (float4*)Alo, N4);
    gemm_mma<<<dim3(4, 32), 256, GSMEM>>>(1, Ahi, Alo, bq, bk, bv, bs1, bo, out);
}

// round 6
// speedup vs baseline: 1.1554x; 1.1554x over previous
#include <cuda_runtime.h>
#include <math_constants.h>
#include <cstdint>

#define SB   2
#define SS   2048
#define SD   512
#define SH   8
#define SHD  64
#define KTOP 307
#define RC   16
#define HWIN 16
#define MROWS (SB*SS)           // 4096
#define QT   ((KTOP + 31) / 32) // 10 query tiles per (b,h)

typedef unsigned long long ull;

// ---------------- f32x2 helpers ---------------------------------------------------
__device__ __forceinline__ void fma2(ull& acc, ull a, ull b) {
    asm("fma.rn.f32x2 %0, %1, %2, %0;" : "+l"(acc) : "l"(a), "l"(b));
}
__device__ __forceinline__ ull mul2(ull a, ull b) {
    ull r; asm("mul.rn.f32x2 %0, %1, %2;" : "=l"(r) : "l"(a), "l"(b)); return r;
}
__device__ __forceinline__ ull pack2(float x, float y) {
    ull r; asm("mov.b64 %0, {%1, %2};" : "=l"(r) : "f"(x), "f"(y)); return r;
}
__device__ __forceinline__ float2 unpack2(ull v) {
    float2 r; asm("mov.b64 {%0, %1}, %2;" : "=f"(r.x), "=f"(r.y) : "l"(v)); return r;
}

// truncation split: hi keeps top-11 mantissa bits (tf32-exact), lo = a - hi (exact fp32;
// MMA HW truncates lo's low bits internally). 1 LOP + 1 FADD, no cvt.
__device__ __forceinline__ void tsplit(float a, float& h, float& l) {
    h = __uint_as_float(__float_as_uint(a) & 0xFFFFE000u);
    l = a - h;
}

// mma.sync m16n8k8 tf32: D(16x8,f32) += A(16x8,tf32) * B(8x8,tf32)
#define MMA8(c, a, b) \
    asm volatile("mma.sync.aligned.m16n8k8.row.col.f32.tf32.tf32.f32 " \
        "{%0,%1,%2,%3},{%4,%5,%6,%7},{%8,%9},{%0,%1,%2,%3};" \
        : "+f"((c)[0]), "+f"((c)[1]), "+f"((c)[2]), "+f"((c)[3]) \
        : "r"((a)[0]), "r"((a)[1]), "r"((a)[2]), "r"((a)[3]), \
          "r"((b)[0]), "r"((b)[1]))

// ---------------- scratch --------------------------------------------------------
__device__ float g_Q  [(size_t)SB*SS*SD];
__device__ float g_K  [(size_t)SB*SS*SD];
__device__ float g_V  [(size_t)SB*SS*SD];
__device__ float g_H1 [(size_t)SB*SS*(SD/2)];
__device__ float g_IMP[SB*SS];
__device__ int   g_FLAG[SB*SS];
__device__ int   g_LIST[SB*KTOP];
__device__ float g_ATT[(size_t)SB*SS*SD];
__device__ float g_Wt [(size_t)2304*SD];   // transposed fp32: Wq 0, Wk 512, Wv 1024, Ws1 1536, Wo 1792

// ---------------- weight transpose (2 matrices per launch via blockIdx.z) ---------
__global__ void wtrans(const float* __restrict__ W1, int N1, int base1,
                       const float* __restrict__ W2, int N2, int base2)
{
    const float* W = blockIdx.z ? W2 : W1;
    int N = blockIdx.z ? N2 : N1;
    int base = blockIdx.z ? base2 : base1;
    int n0 = blockIdx.x * 32;
    if (n0 >= N) return;
    __shared__ float t[32][33];
    int k0 = blockIdx.y * 32;
    int tx = threadIdx.x, ty = threadIdx.y;   // 32 x 8
#pragma unroll
    for (int i = 0; i < 4; i++)
        t[ty + i * 8][tx] = W[(size_t)(k0 + ty + i * 8) * N + n0 + tx];
    __syncthreads();
#pragma unroll
    for (int i = 0; i < 4; i++)
        g_Wt[(size_t)(base + n0 + ty + i * 8) * SD + k0 + tx] = t[tx][ty + i * 8];
}

// ================= mma.sync tf32 GEMM: 128x128 tile, BK=16, 8 warps ===============
// split-on-load: reads fp32 A (x or ATT) and fp32 g_Wt, splits hi/lo in registers.
#define GP    20
#define GARR  (128 * GP)            // 2560 floats
#define GSTG  (4 * GARR)            // 10240 floats per stage
#define GSMEM (2 * GSTG * 4)        // 81920 bytes

__global__ void __launch_bounds__(256) gemm_mma(int mode,
    const float* __restrict__ Asrc,
    const float* __restrict__ bq, const float* __restrict__ bk,
    const float* __restrict__ bv, const float* __restrict__ bs1,
    const float* __restrict__ bo, float* __restrict__ Oo)
{
    extern __shared__ __align__(16) float smf[];
    int nt = blockIdx.x, m0 = blockIdx.y * 128;
    int tid = threadIdx.x, wid = tid >> 5, lane = tid & 31;
    int wm = wid & 3, wn = wid >> 2;
    int g = lane >> 2, t4 = lane & 3;

    float* C; const float* bias; int Nc, cbase, wtrow, relu = 0, fourth = 0;
    if (mode == 0) {
        if (nt < 4)       { C = g_Q;  bias = bq;  Nc = 512; cbase = nt * 128; }
        else if (nt < 8)  { C = g_K;  bias = bk;  Nc = 512; cbase = (nt - 4) * 128; }
        else if (nt < 12) { C = g_V;  bias = bv;  Nc = 512; cbase = (nt - 8) * 128; }
        else              { C = g_H1; bias = bs1; Nc = 256; cbase = (nt - 12) * 128; relu = 1; fourth = 1; }
        wtrow = nt * 128;
    } else {
        C = Oo; bias = bo; Nc = 512; cbase = nt * 128; wtrow = 1792 + nt * 128;
    }

    float c[2][8][4];
#pragma unroll
    for (int mt = 0; mt < 2; mt++)
#pragma unroll
        for (int j = 0; j < 8; j++)
#pragma unroll
            for (int q = 0; q < 4; q++) c[mt][j][q] = 0.f;

    // loader coords: 512 float4 per matrix, 2 per thread
    int u0 = tid, u1 = tid + 256;
    int r0 = u0 >> 2, c0_ = (u0 & 3) * 4;
    int r1 = u1 >> 2, c1_ = (u1 & 3) * 4;

    const float* pA = Asrc + (size_t)m0 * SD;
    const float* pB = g_Wt + (size_t)wtrow * SD;

    float4 fa0, fa1, fb0, fb1;
    fa0 = *(const float4*)(pA + (size_t)r0 * SD + c0_);
    fa1 = *(const float4*)(pA + (size_t)r1 * SD + c1_);
    fb0 = *(const float4*)(pB + (size_t)r0 * SD + c0_);
    fb1 = *(const float4*)(pB + (size_t)r1 * SD + c1_);

#pragma unroll 1
    for (int it = 0; it < 32; it++) {
        float* st = smf + (it & 1) * GSTG;
        {
            float4 h, l;
            tsplit(fa0.x, h.x, l.x); tsplit(fa0.y, h.y, l.y);
            tsplit(fa0.z, h.z, l.z); tsplit(fa0.w, h.w, l.w);
            *(float4*)(st + 0 * GARR + r0 * GP + c0_) = h;
            *(float4*)(st + 1 * GARR + r0 * GP + c0_) = l;
            tsplit(fa1.x, h.x, l.x); tsplit(fa1.y, h.y, l.y);
            tsplit(fa1.z, h.z, l.z); tsplit(fa1.w, h.w, l.w);
            *(float4*)(st + 0 * GARR + r1 * GP + c1_) = h;
            *(float4*)(st + 1 * GARR + r1 * GP + c1_) = l;
            tsplit(fb0.x, h.x, l.x); tsplit(fb0.y, h.y, l.y);
            tsplit(fb0.z, h.z, l.z); tsplit(fb0.w, h.w, l.w);
            *(float4*)(st + 2 * GARR + r0 * GP + c0_) = h;
            *(float4*)(st + 3 * GARR + r0 * GP + c0_) = l;
            tsplit(fb1.x, h.x, l.x); tsplit(fb1.y, h.y, l.y);
            tsplit(fb1.z, h.z, l.z); tsplit(fb1.w, h.w, l.w);
            *(float4*)(st + 2 * GARR + r1 * GP + c1_) = h;
            *(float4*)(st + 3 * GARR + r1 * GP + c1_) = l;
        }
        __syncthreads();

        if (it + 1 < 32) {   // prefetch next slab
            int k0 = (it + 1) * 16;
            fa0 = *(const float4*)(pA + (size_t)r0 * SD + k0 + c0_);
            fa1 = *(const float4*)(pA + (size_t)r1 * SD + k0 + c1_);
            fb0 = *(const float4*)(pB + (size_t)r0 * SD + k0 + c0_);
            fb1 = *(const float4*)(pB + (size_t)r1 * SD + k0 + c1_);
        }

        const uint32_t* uAh = (const uint32_t*)(st + 0 * GARR);
        const uint32_t* uAl = (const uint32_t*)(st + 1 * GARR);
        const uint32_t* uBh = (const uint32_t*)(st + 2 * GARR);
        const uint32_t* uBl = (const uint32_t*)(st + 3 * GARR);

#pragma unroll
        for (int ks = 0; ks < 2; ks++) {
            int kc = ks * 8 + t4;
            uint32_t ah[2][4], al[2][4];
#pragma unroll
            for (int mt = 0; mt < 2; mt++) {
                int rr = (wm * 32 + mt * 16 + g) * GP;
                ah[mt][0] = uAh[rr + kc];            ah[mt][1] = uAh[rr + 8 * GP + kc];
                ah[mt][2] = uAh[rr + kc + 4];        ah[mt][3] = uAh[rr + 8 * GP + kc + 4];
                al[mt][0] = uAl[rr + kc];            al[mt][1] = uAl[rr + 8 * GP + kc];
                al[mt][2] = uAl[rr + kc + 4];        al[mt][3] = uAl[rr + 8 * GP + kc + 4];
            }
#pragma unroll
            for (int grp = 0; grp < 2; grp++) {
                uint32_t bh[4][2], bl[4][2];
#pragma unroll
                for (int jj = 0; jj < 4; jj++) {
                    int nr = (wn * 64 + (grp * 4 + jj) * 8 + g) * GP;
                    bh[jj][0] = uBh[nr + kc]; bh[jj][1] = uBh[nr + kc + 4];
                    bl[jj][0] = uBl[nr + kc]; bl[jj][1] = uBl[nr + kc + 4];
                }
#pragma unroll
                for (int jj = 0; jj < 4; jj++)
#pragma unroll
                    for (int mt = 0; mt < 2; mt++) {
                        float* cc = c[mt][grp * 4 + jj];
                        MMA8(cc, ah[mt], bh[jj]);
                        MMA8(cc, ah[mt], bl[jj]);
                        MMA8(cc, al[mt], bh[jj]);
                        if (fourth) MMA8(cc, al[mt], bl[jj]);
                    }
            }
        }
        __syncthreads();
    }

    // epilogue
#pragma unroll
    for (int mt = 0; mt < 2; mt++) {
        int rowa = m0 + wm * 32 + mt * 16 + g;
#pragma unroll
        for (int j = 0; j < 8; j++) {
            int colg = cbase + wn * 64 + j * 8 + t4 * 2;
            float2 bb = *(const float2*)&bias[colg];
            float2 o0 = make_float2(c[mt][j][0] + bb.x, c[mt][j][1] + bb.y);
            float2 o1 = make_float2(c[mt][j][2] + bb.x, c[mt][j][3] + bb.y);
            if (relu) {
                o0.x = fmaxf(o0.x, 0.f); o0.y = fmaxf(o0.y, 0.f);
                o1.x = fmaxf(o1.x, 0.f); o1.y = fmaxf(o1.y, 0.f);
            }
            *(float2*)&C[(size_t)rowa * Nc + colg]       = o0;
            *(float2*)&C[(size_t)(rowa + 8) * Nc + colg] = o1;
        }
    }
}

// ---------------- importance -----------------------------------------------------
__global__ void imp_kernel(const float* __restrict__ H1, const float* __restrict__ Ws2,
                           const float* __restrict__ bs2, float* __restrict__ IMP)
{
    int row = blockIdx.x * 8 + (threadIdx.x >> 5);
    int l   = threadIdx.x & 31;
    const float* h = H1 + (size_t)row * 256;
    float acc = 0.f;
#pragma unroll
    for (int c = l; c < 256; c += 32) acc += h[c] * Ws2[c];
#pragma unroll
    for (int o = 16; o; o >>= 1) acc += __shfl_xor_sync(0xffffffffu, acc, o);
    if (l == 0) {
        float z = acc + bs2[0];
        IMP[row] = 1.f / (1.f + __expf(-z));
    }
}

// ---------------- top-k ------------------------------------------------------------
__global__ void topk_flag(const float* __restrict__ IMP, int* __restrict__ FLAG)
{
    int b = blockIdx.x, chunk = blockIdx.y;
    __shared__ float s[SS];
    for (int i = threadIdx.x; i < SS; i += 256) s[i] = IMP[b * SS + i];
    __syncthreads();
    int i = chunk * 256 + threadIdx.x;
    float vi = s[i];
    int cnt = 0;
#pragma unroll 8
    for (int j = 0; j < SS; j++) {
        float vj = s[j];
        cnt += (vj > vi) || (vj == vi && j < i);
    }
    FLAG[b * SS + i] = (cnt < KTOP) ? 1 : 0;
}

__global__ void topk_compact(const int* __restrict__ FLAG, int* __restrict__ LIST)
{
    int b = blockIdx.x;
    __shared__ int f[SS];
    __shared__ int cs[256];
    for (int i = threadIdx.x; i < SS; i += 256) f[i] = FLAG[b * SS + i];
    __syncthreads();
    int t = threadIdx.x;
    int sum = 0;
#pragma unroll
    for (int j = 0; j < 8; j++) sum += f[t * 8 + j];
    cs[t] = sum;
    __syncthreads();
#pragma unroll
    for (int off = 1; off < 256; off <<= 1) {
        int v = (t >= off) ? cs[t - off] : 0;
        __syncthreads();
        cs[t] += v;
        __syncthreads();
    }
    int pos = cs[t] - sum;
#pragma unroll
    for (int j = 0; j < 8; j++) {
        int i = t * 8 + j;
        if (f[i]) LIST[b * KTOP + pos++] = i;
    }
}

// ---------------- kernel A: non-important rows (<=33 keys), coalesced QK ---------
__global__ void attn_sparse(const float* __restrict__ Q, const float* __restrict__ K,
                            const float* __restrict__ V, const int* __restrict__ rand_idx,
                            const int* __restrict__ FLAG, float* __restrict__ ATT)
{
    int bi = blockIdx.x;
    if (FLAG[bi]) return;
    int b = bi >> 11, i = bi & (SS - 1);

    __shared__ float qsh[SD];
    __shared__ int   list[40];
    __shared__ int   nk_sh;
    __shared__ float p[SH][64];

    const float* qrow = Q + (size_t)bi * SD;
    for (int t = threadIdx.x; t < SD; t += 256) qsh[t] = qrow[t];

    if (threadIdx.x == 0) {
        int lo = i - HWIN; if (lo < 0) lo = 0;
        int n = 0;
        for (int j = lo; j <= i; j++) list[n++] = j;
        int nw = n;
        for (int r = 0; r < RC; r++) {
            int j = rand_idx[(size_t)bi * RC + r];
            if (j <= i && j < lo) {
                bool dup = false;
                for (int t = nw; t < n; t++) if (list[t] == j) { dup = true; break; }
                if (!dup) list[n++] = j;
            }
        }
        nk_sh = n;
    }
    __syncthreads();

    int h = threadIdx.x >> 5, l = threadIdx.x & 31;
    int n = nk_sh;
    int kk = l >> 3, l8 = l & 7;

    // QK: 4 keys per warp-pass, 8 lanes per key reading a contiguous 256B row slice
    const float* qh8 = qsh + h * SHD + l8 * 8;
    float4 q0 = *(const float4*)qh8, q1 = *(const float4*)(qh8 + 4);
    for (int t0 = 0; t0 < n; t0 += 4) {
        int idx = t0 + kk;
        int j = list[idx < n ? idx : 0];
        const float* kr = K + ((size_t)b * SS + j) * SD + h * SHD + l8 * 8;
        float4 k0 = *(const float4*)kr, k1 = *(const float4*)(kr + 4);
        ull acc = 0ull;
        fma2(acc, pack2(k0.x, k0.y), pack2(q0.x, q0.y));
        fma2(acc, pack2(k0.z, k0.w), pack2(q0.z, q0.w));
        fma2(acc, pack2(k1.x, k1.y), pack2(q1.x, q1.y));
        fma2(acc, pack2(k1.z, k1.w), pack2(q1.z, q1.w));
        float2 f = unpack2(acc);
        float s = f.x + f.y;
        s += __shfl_xor_sync(0xffffffffu, s, 1);
        s += __shfl_xor_sync(0xffffffffu, s, 2);
        s += __shfl_xor_sync(0xffffffffu, s, 4);
        if (l8 == 0 && idx < n) p[h][idx] = s * 0.125f;
    }
    __syncwarp();

    float s0 = (l < n)      ? p[h][l]      : -CUDART_INF_F;
    float s1 = (l + 32 < n) ? p[h][l + 32] : -CUDART_INF_F;
    float mx = fmaxf(s0, s1);
#pragma unroll
    for (int o = 16; o; o >>= 1) mx = fmaxf(mx, __shfl_xor_sync(0xffffffffu, mx, o));
    float e0 = (l < n)      ? __expf(s0 - mx) : 0.f;
    float e1 = (l + 32 < n) ? __expf(s1 - mx) : 0.f;
    float sum = e0 + e1;
#pragma unroll
    for (int o = 16; o; o >>= 1) sum += __shfl_xor_sync(0xffffffffu, sum, o);
    float inv = 1.f / sum;
    p[h][l] = e0;
    p[h][l + 32] = e1;
    __syncwarp();

    ull a0p = 0ull, a1p = 0ull;
    float a0t = 0.f, a1t = 0.f;
    int t = 0;
    for (; t + 1 < n; t += 2) {
        const float* v0 = V + ((size_t)b * SS + list[t])     * SD + h * SHD;
        const float* v1 = V + ((size_t)b * SS + list[t + 1]) * SD + h * SHD;
        ull pp = pack2(p[h][t], p[h][t + 1]);
        fma2(a0p, pp, pack2(v0[l],      v1[l]));
        fma2(a1p, pp, pack2(v0[l + 32], v1[l + 32]));
    }
    if (t < n) {
        const float* v0 = V + ((size_t)b * SS + list[t]) * SD + h * SHD;
        float pj = p[h][t];
        a0t = pj * v0[l];
        a1t = pj * v0[l + 32];
    }
    float2 fa0 = unpack2(a0p), fa1 = unpack2(a1p);
    float* orow = ATT + (size_t)bi * SD + h * SHD;
    orow[l]      = (fa0.x + fa0.y + a0t) * inv;
    orow[l + 32] = (fa1.x + fa1.y + a1t) * inv;
}

// ---------------- kernel B: flash-style q-tiled dense rows -----------------------
__global__ void attn_dense(const float* __restrict__ Q, const float* __restrict__ K,
                           const float* __restrict__ V, const int* __restrict__ LIST,
                           float* __restrict__ ATT)
{
    int qt = blockIdx.x, b = blockIdx.y, h = blockIdx.z;
    __shared__ float2 Qs2[32][32];
    __shared__ float2 Ks2[32][33];
    __shared__ float  Vs[32][64];
    __shared__ float  Ps[32][34];
    __shared__ int    qi[32];

    int tid = threadIdx.x, w = tid >> 5, l = tid & 31;
    int base = qt * 32;
    int nq = KTOP - base; if (nq > 32) nq = 32;
    if (tid < 32)
        qi[tid] = (tid < nq) ? LIST[b * KTOP + base + tid] : -1;
    __syncthreads();
    int imax = qi[nq - 1];

    int row = tid >> 3, d0 = (tid & 7) * 8;
    {
        int q = qi[row]; int qs = q < 0 ? 0 : q;
        const float* src = Q + ((size_t)b * SS + qs) * SD + h * SHD + d0;
        float4 a = *(const float4*)src;
        float4 c = *(const float4*)(src + 4);
        int dp = d0 >> 1;
        Qs2[row][dp + 0] = make_float2(a.x, a.y);
        Qs2[row][dp + 1] = make_float2(a.z, a.w);
        Qs2[row][dp + 2] = make_float2(c.x, c.y);
        Qs2[row][dp + 3] = make_float2(c.z, c.w);
    }

    int qg[4];
    float m[4], lsum[4];
    ull a0p[4], a1p[4];
#pragma unroll
    for (int c = 0; c < 4; c++) {
        qg[c] = qi[w * 4 + c];
        m[c] = -CUDART_INF_F; lsum[c] = 0.f; a0p[c] = 0ull; a1p[c] = 0ull;
    }

    for (int j0 = 0; j0 <= imax; j0 += 32) {
        __syncthreads();
        {
            int j = j0 + row;
            const float* kp = K + ((size_t)b * SS + j) * SD + h * SHD + d0;
            float4 ka = *(const float4*)kp;
            float4 kb = *(const float4*)(kp + 4);
            int dp = d0 >> 1;
            Ks2[dp + 0][row] = make_float2(ka.x, ka.y);
            Ks2[dp + 1][row] = make_float2(ka.z, ka.w);
            Ks2[dp + 2][row] = make_float2(kb.x, kb.y);
            Ks2[dp + 3][row] = make_float2(kb.z, kb.w);
            const float* vp = V + ((size_t)b * SS + j) * SD + h * SHD + d0;
            *(float4*)&Vs[row][d0]     = *(const float4*)vp;
            *(float4*)&Vs[row][d0 + 4] = *(const float4*)(vp + 4);
        }
        __syncthreads();

        int jg = j0 + l;
        ull acc2[4] = {0ull, 0ull, 0ull, 0ull};
        const ull* Qu = (const ull*)Qs2;
        const ull* Ku = (const ull*)Ks2;
#pragma unroll
        for (int dp = 0; dp < 32; dp++) {
            ull kp = Ku[dp * 33 + l];
#pragma unroll
            for (int c = 0; c < 4; c++)
                fma2(acc2[c], Qu[(w * 4 + c) * 32 + dp], kp);
        }
#pragma unroll
        for (int c = 0; c < 4; c++) {
            float2 sf = unpack2(acc2[c]);
            bool ok = (jg <= qg[c]);
            float sc = ok ? (sf.x + sf.y) * 0.125f : -CUDART_INF_F;
            float tm = sc;
#pragma unroll
            for (int o = 16; o; o >>= 1) tm = fmaxf(tm, __shfl_xor_sync(0xffffffffu, tm, o));
            float newm = fmaxf(m[c], tm);
            float pv = 0.f;
            if (newm != -CUDART_INF_F) {
                pv = ok ? __expf(sc - newm) : 0.f;
                float ps = pv;
#pragma unroll
                for (int o = 16; o; o >>= 1) ps += __shfl_xor_sync(0xffffffffu, ps, o);
                float scale = (m[c] == -CUDART_INF_F) ? 0.f : __expf(m[c] - newm);
                lsum[c] = lsum[c] * scale + ps;
                ull ss = pack2(scale, scale);
                a0p[c] = mul2(a0p[c], ss);
                a1p[c] = mul2(a1p[c], ss);
                m[c] = newm;
            }
            Ps[w * 4 + c][l] = pv;
        }
        __syncwarp();
#pragma unroll
        for (int jp = 0; jp < 16; jp++) {
            int j = jp * 2;
            ull vpa = pack2(Vs[j][l],      Vs[j + 1][l]);
            ull vpb = pack2(Vs[j][l + 32], Vs[j + 1][l + 32]);
#pragma unroll
            for (int c = 0; c < 4; c++) {
                ull pp = *(const ull*)&Ps[w * 4 + c][j];
                fma2(a0p[c], pp, vpa);
                fma2(a1p[c], pp, vpb);
            }
        }
    }

#pragma unroll
    for (int c = 0; c < 4; c++) {
        if (qg[c] >= 0) {
            float inv = 1.f / lsum[c];
            float2 fa = unpack2(a0p[c]);
            float2 fb = unpack2(a1p[c]);
            float* orow = ATT + ((size_t)b * SS + qg[c]) * SD + h * SHD;
            orow[l]      = (fa.x + fa.y) * inv;
            orow[l + 32] = (fb.x + fb.y) * inv;
        }
    }
}

// ---------------- launch ---------------------------------------------------------
extern "C" void kernel_launch(void* const* d_in, const int* in_sizes, int n_in,
                              void* d_out, int out_size)
{
    const float* x    = (const float*)d_in[0];
    const float* Wq   = (const float*)d_in[1];
    const float* bq   = (const float*)d_in[2];
    const float* Wk   = (const float*)d_in[3];
    const float* bk   = (const float*)d_in[4];
    const float* Wv   = (const float*)d_in[5];
    const float* bv   = (const float*)d_in[6];
    const float* Wo   = (const float*)d_in[7];
    const float* bo   = (const float*)d_in[8];
    const float* Ws1  = (const float*)d_in[9];
    const float* bs1  = (const float*)d_in[10];
    const float* Ws2  = (const float*)d_in[11];
    const float* bs2  = (const float*)d_in[12];
    const int*   ridx = (const int*)  d_in[13];
    float* out = (float*)d_out;

    float *Q, *K, *V, *H1, *IMP, *ATT;
    int *FLAG, *LIST;
    cudaGetSymbolAddress((void**)&Q,   g_Q);
    cudaGetSymbolAddress((void**)&K,   g_K);
    cudaGetSymbolAddress((void**)&V,   g_V);
    cudaGetSymbolAddress((void**)&H1,  g_H1);
    cudaGetSymbolAddress((void**)&IMP, g_IMP);
    cudaGetSymbolAddress((void**)&ATT, g_ATT);
    cudaGetSymbolAddress((void**)&FLAG, g_FLAG);
    cudaGetSymbolAddress((void**)&LIST, g_LIST);

    cudaFuncSetAttribute(gemm_mma, cudaFuncAttributeMaxDynamicSharedMemorySize, GSMEM);

    // launches 1-3: weight transposes (gemm_mma mode0 is launch #4 -> profiled)
    wtrans<<<dim3(16, 16, 2), dim3(32, 8)>>>(Wq, 512, 0,    Wk,  512, 512);
    wtrans<<<dim3(16, 16, 2), dim3(32, 8)>>>(Wv, 512, 1024, Ws1, 256, 1536);
    wtrans<<<dim3(16, 16, 1), dim3(32, 8)>>>(Wo, 512, 1792, Wo,  512, 1792);

    gemm_mma<<<dim3(14, 32), 256, GSMEM>>>(0, x, bq, bk, bv, bs1, bo, out);

    imp_kernel<<<MROWS / 8, 256>>>(H1, Ws2, bs2, IMP);
    topk_flag<<<dim3(SB, 8), 256>>>(IMP, FLAG);
    topk_compact<<<SB, 256>>>(FLAG, LIST);

    attn_sparse<<<MROWS, 256>>>(Q, K, V, ridx, FLAG, ATT);
    attn_dense<<<dim3(QT, SB, SH), 256>>>(Q, K, V, LIST, ATT);

    gemm_mma<<<dim3(4, 32), 256, GSMEM>>>(1, ATT, bq, bk, bv, bs1, bo, out);
}